// round 5
// baseline (speedup 1.0000x reference)
#include <cuda_runtime.h>

// ShiftedConv2d_25872882991120 — R5
//
// Analytic collapse (bit-exact since R1): output is all zeros except
//   out[b, c*16+s, 0, 0] = tens[b,c,127,127] * filters[s,0,0,0]
// for each s with shifts[s] == (7,7).
//
// R4 post-mortem: four distinct write paths all land at 37.3-38.6 us for
// the 256 MiB streaming store -> DRAM-write roofline (payload ~7.2 TB/s,
// ~90% of spec). R5 micro-tune: 8 streaming STG.128 per thread (8192
// blocks, half the waves of R4), fixup still folded into the fill.

#define PLANES     4096                    // B*C*S = 8*32*16
#define PLANE_V4   4096                    // 128*128 floats / 4
#define OUT_V4     (PLANES * PLANE_V4)     // 16,777,216 float4 (256 MiB)
#define THREADS    256
#define V4_PER_THR 8                       // chunk = 2048 float4 per block

__global__ void __launch_bounds__(THREADS)
shifted_conv_fill_cs8_kernel(const float* __restrict__ tens,
                             const float* __restrict__ filters,
                             const int*   __restrict__ shifts,
                             float4* __restrict__ out)
{
    const unsigned base = blockIdx.x * (THREADS * V4_PER_THR) + threadIdx.x;

    const float4 z = make_float4(0.f, 0.f, 0.f, 0.f);
    float4 v0 = z;

    // Plane heads are at v4 offsets k*4096. Chunk size 2048 divides 4096,
    // so a head is the chunk's first element iff blockIdx.x is even.
    if (threadIdx.x == 0 && (blockIdx.x & 1u) == 0u) {
        const unsigned plane = blockIdx.x >> 1;
        const unsigned s = plane & 15u;
        const int sh0 = shifts[2u * s];
        const int sh1 = shifts[2u * s + 1u];
        if (sh0 == 7 && sh1 == 7) {
            const unsigned c = (plane >> 4) & 31u;
            const unsigned b = plane >> 9;
            const unsigned n = b * 32u + c;
            v0.x = tens[(n * 128u + 127u) * 128u + 127u] * filters[s * 49u];
        }
    }

    // 8 independent streaming STG.128 per thread; each warp iteration is a
    // contiguous 2 KB burst (full 128 B lines, no write-allocate reads).
    __stcs(out + base,               v0);
    #pragma unroll
    for (int i = 1; i < V4_PER_THR; i++)
        __stcs(out + base + i * THREADS, z);
}

extern "C" void kernel_launch(void* const* d_in, const int* in_sizes, int n_in,
                              void* d_out, int out_size)
{
    const float* tens    = (const float*)d_in[0];
    const float* filters = (const float*)d_in[1];
    const int*   shifts  = (const int*)d_in[2];
    float4*      out     = (float4*)d_out;

    (void)in_sizes; (void)n_in; (void)out_size;

    // 16,777,216 v4 / (256 thr * 8 v4) = 8192 blocks, exact cover.
    shifted_conv_fill_cs8_kernel<<<OUT_V4 / (THREADS * V4_PER_THR), THREADS>>>(
        tens, filters, shifts, out);
}